// round 10
// baseline (speedup 1.0000x reference)
#include <cuda_runtime.h>
#include <cstdint>

#define B_SZ 8
#define SEQ 4096
#define DM 1024
#define DS 64
#define LTAPS 64

#define TBLK 128    // time steps per tile
#define NTILE 4     // tiles per CTA (sequential in t)
#define CBLK 64     // channels per block (32 float2 pairs)
#define TT 8        // outputs per thread
#define NTHR 512    // conv block size
#define G 8         // tap group size
#define ROWS (TBLK + 64)   // 192 rows per u tile (halo 32 each side)

__device__ float g_part[64 * DS];   // partial C column sums
__device__ float g_K[LTAPS * DM];   // K[l][c], channel-contiguous

// ---------------- packed f32x2 ops (Blackwell FFMA2, PTX-only) ----------------

__device__ __forceinline__ float2 ffma2(float2 a, float2 b, float2 c) {
    float2 d;
    asm("fma.rn.f32x2 %0, %1, %2, %3;"
        : "=l"(*reinterpret_cast<unsigned long long*>(&d))
        : "l"(*reinterpret_cast<const unsigned long long*>(&a)),
          "l"(*reinterpret_cast<const unsigned long long*>(&b)),
          "l"(*reinterpret_cast<const unsigned long long*>(&c)));
    return d;
}

__device__ __forceinline__ float2 fmul2(float2 a, float2 b) {
    float2 d;
    asm("mul.rn.f32x2 %0, %1, %2;"
        : "=l"(*reinterpret_cast<unsigned long long*>(&d))
        : "l"(*reinterpret_cast<const unsigned long long*>(&a)),
          "l"(*reinterpret_cast<const unsigned long long*>(&b)));
    return d;
}

// ---------------- prep: stage A — partial column sums of C (coalesced) --------
__global__ __launch_bounds__(64)
void csum_part_kernel(const float* __restrict__ C) {
    const int d = threadIdx.x;
    const float* __restrict__ Cp = C + (size_t)blockIdx.x * 16 * DS + d;
    float s = 0.f;
    #pragma unroll
    for (int i = 0; i < 16; ++i) s += Cp[(size_t)i * DS];
    g_part[blockIdx.x * DS + d] = s;
}

// ---------------- prep: stage B + K build (f32x2 geometric chains) ------------
__global__ __launch_bounds__(64)
void kbuild_kernel(const float* __restrict__ A,
                   const float* __restrict__ Bp,
                   const float* __restrict__ log_dt) {
    __shared__ float sh_csum[DS];
    const int tid = threadIdx.x;

    {
        float s = 0.f;
        #pragma unroll 16
        for (int j = 0; j < 64; ++j) s += g_part[j * DS + tid];
        sh_csum[tid] = s;
    }
    __syncthreads();

    const int c = blockIdx.x * 64 + tid;
    const float dt = expf(log_dt[c]);

    float2 k2[LTAPS / 2];
    #pragma unroll
    for (int i = 0; i < LTAPS / 2; ++i) k2[i] = make_float2(0.f, 0.f);

    #pragma unroll 2
    for (int d = 0; d < DS; ++d) {
        const float w  = sh_csum[d] * Bp[(size_t)d * DM + c];
        const float r  = expf(A[d] * dt);
        const float r2 = r * r;
        float2 p = make_float2(w, w * r);
        const float2 rr = make_float2(r2, r2);
        #pragma unroll
        for (int i = 0; i < LTAPS / 2; ++i) {
            k2[i].x += p.x;
            k2[i].y += p.y;
            p = fmul2(p, rr);
        }
    }

    #pragma unroll
    for (int i = 0; i < LTAPS / 2; ++i) {
        g_K[(size_t)(2 * i)     * DM + c] = k2[i].x;
        g_K[(size_t)(2 * i + 1) * DM + c] = k2[i].y;
    }
}

// ---------------- cp.async helpers ----------------

__device__ __forceinline__ void cp_async8(void* smem_dst, const void* gsrc,
                                          unsigned src_size) {
    unsigned daddr = (unsigned)__cvta_generic_to_shared(smem_dst);
    asm volatile("cp.async.ca.shared.global [%0], [%1], 8, %2;"
                 :: "r"(daddr), "l"(gsrc), "r"(src_size));
}

__device__ __forceinline__ void cp_commit() {
    asm volatile("cp.async.commit_group;");
}

template <int N>
__device__ __forceinline__ void cp_wait() {
    asm volatile("cp.async.wait_group %0;" :: "n"(N));
}

// ---------------- conv kernel ----------------
// y[b,t,c] = D[c]*u[b,t,c] + sum_{l=0}^{63} K[l,c] * u[b, t+31-l, c]
// Each CTA: 4 consecutive t-tiles, cp.async double-buffered u, shK loaded once.
// Compute body is the proven R5 structure (TT=8, 512 thr, shift window).

__global__ __launch_bounds__(NTHR, 2)
void conv_kernel(const float* __restrict__ u,
                 const float* __restrict__ Dp,
                 float* __restrict__ y) {
    extern __shared__ float2 dyn[];
    float2 (*buf0)[CBLK / 2] = reinterpret_cast<float2(*)[CBLK / 2]>(dyn);
    float2 (*buf1)[CBLK / 2] = reinterpret_cast<float2(*)[CBLK / 2]>(dyn + ROWS * 32);
    float2 (*shK)[CBLK / 2]  = reinterpret_cast<float2(*)[CBLK / 2]>(dyn + 2 * ROWS * 32);

    const int b     = blockIdx.z;
    const int tbase = blockIdx.x * (TBLK * NTILE);
    const int c0    = blockIdx.y * CBLK;
    const int tid   = threadIdx.x;

    const float2* __restrict__ u2 =
        reinterpret_cast<const float2*>(u + (size_t)b * SEQ * DM + c0);

    // issue shK (once) + tile 0 as group 0
    {
        const float2* __restrict__ gK2 =
            reinterpret_cast<const float2*>(g_K) + (c0 >> 1);
        #pragma unroll
        for (int it = 0; it < LTAPS * 32 / NTHR; ++it) {
            int i  = it * NTHR + tid;
            int l  = i >> 5;
            int pp = i & 31;
            cp_async8(&shK[l][pp], gK2 + (size_t)l * (DM / 2) + pp, 8);
        }
        #pragma unroll
        for (int it = 0; it < ROWS * 32 / NTHR; ++it) {
            int i  = it * NTHR + tid;
            int tt = i >> 5;
            int pp = i & 31;
            int t  = tbase - 32 + tt;
            bool valid = (t >= 0) && (t < SEQ);
            cp_async8(&buf0[tt][pp],
                      u2 + (size_t)(valid ? t : 0) * (DM / 2) + pp,
                      valid ? 8u : 0u);
        }
        cp_commit();
    }

    const int p   = tid & 31;          // channel pair
    const int tg  = tid >> 5;          // time group (0..15)
    const int lt0 = 32 + tg * TT;      // tile-local time index of output j=0

    const float2 d2 = reinterpret_cast<const float2*>(Dp + c0)[p];

    float2* __restrict__ y2 =
        reinterpret_cast<float2*>(y + (size_t)b * SEQ * DM + c0);

    #pragma unroll
    for (int k = 0; k < NTILE; ++k) {
        float2 (*cur)[CBLK / 2] = (k & 1) ? buf1 : buf0;

        // prefetch tile k+1 into the other buffer
        if (k + 1 < NTILE) {
            float2 (*nxt)[CBLK / 2] = ((k + 1) & 1) ? buf1 : buf0;
            const int t0n = tbase + (k + 1) * TBLK;
            #pragma unroll
            for (int it = 0; it < ROWS * 32 / NTHR; ++it) {
                int i  = it * NTHR + tid;
                int tt = i >> 5;
                int pp = i & 31;
                int t  = t0n - 32 + tt;
                bool valid = (t >= 0) && (t < SEQ);
                cp_async8(&nxt[tt][pp],
                          u2 + (size_t)(valid ? t : 0) * (DM / 2) + pp,
                          valid ? 8u : 0u);
            }
            cp_commit();
            cp_wait<1>();    // tile k (and shK) complete
        } else {
            cp_wait<0>();
        }
        __syncthreads();

        // ---- compute tile k (R5 body) ----
        const int t0 = tbase + k * TBLK;

        float2 acc[TT];
        #pragma unroll
        for (int j = 0; j < TT; ++j)
            acc[j] = fmul2(d2, cur[lt0 + j][p]);

        float2 w[TT + G - 1];
        const int wb0 = lt0 + 32 - G;   // = lt0 + 24
        #pragma unroll
        for (int i = 0; i < TT + G - 1; ++i) w[i] = cur[wb0 + i][p];

        #pragma unroll
        for (int g = 0; g < LTAPS / G; ++g) {
            if (g > 0) {
                #pragma unroll
                for (int i = TT + G - 2; i >= G; --i) w[i] = w[i - G];
                const int wb = wb0 - g * G;
                #pragma unroll
                for (int i = 0; i < G; ++i) w[i] = cur[wb + i][p];
            }
            #pragma unroll
            for (int e = 0; e < G; ++e) {
                float2 k2 = shK[g * G + e][p];
                #pragma unroll
                for (int j = 0; j < TT; ++j)
                    acc[j] = ffma2(k2, w[j + (G - 1 - e)], acc[j]);
            }
        }

        #pragma unroll
        for (int j = 0; j < TT; ++j) {
            int t = t0 + tg * TT + j;
            y2[(size_t)t * (DM / 2) + p] = acc[j];
        }

        __syncthreads();   // buffer cur is reused for prefetch at k+2
    }
}

// ---------------- launch ----------------

extern "C" void kernel_launch(void* const* d_in, const int* in_sizes, int n_in,
                              void* d_out, int out_size) {
    const float* u      = (const float*)d_in[0];
    const float* A      = (const float*)d_in[1];
    const float* Bp     = (const float*)d_in[2];
    const float* C      = (const float*)d_in[3];
    const float* Dp     = (const float*)d_in[4];
    const float* log_dt = (const float*)d_in[5];
    float* y = (float*)d_out;

    csum_part_kernel<<<64, 64>>>(C);
    kbuild_kernel<<<16, 64>>>(A, Bp, log_dt);

    // dynamic smem: 2 u buffers (2 x 48KB) + shK (16KB) = 112KB
    const int smem_bytes = (2 * ROWS * 32 + LTAPS * 32) * (int)sizeof(float2);
    static bool attr_set = false;
    if (!attr_set) {
        cudaFuncSetAttribute(conv_kernel,
                             cudaFuncAttributeMaxDynamicSharedMemorySize,
                             smem_bytes);
        attr_set = true;
    }

    dim3 grid(SEQ / (TBLK * NTILE), DM / CBLK, B_SZ);  // (8, 16, 8)
    conv_kernel<<<grid, NTHR, smem_bytes>>>(u, Dp, y);
}

// round 11
// speedup vs baseline: 1.0954x; 1.0954x over previous
#include <cuda_runtime.h>
#include <cstdint>

#define B_SZ 8
#define SEQ 4096
#define DM 1024
#define DS 64
#define LTAPS 64

#define TBLK 128   // time steps per block
#define CBLK 64    // channels per block (32 float2 pairs)
#define TT 8       // outputs per thread
#define NTHR 512   // conv block size
#define G 8        // tap group size
#define PITCH 33   // padded u-tile row pitch (float2) for conflict-free pairs

__device__ float g_part[64 * DS];   // partial C column sums
__device__ float g_K[LTAPS * DM];   // K[l][c], channel-contiguous

// ---------------- packed f32x2 ops (Blackwell FFMA2, PTX-only) ----------------

__device__ __forceinline__ float2 ffma2(float2 a, float2 b, float2 c) {
    float2 d;
    asm("fma.rn.f32x2 %0, %1, %2, %3;"
        : "=l"(*reinterpret_cast<unsigned long long*>(&d))
        : "l"(*reinterpret_cast<const unsigned long long*>(&a)),
          "l"(*reinterpret_cast<const unsigned long long*>(&b)),
          "l"(*reinterpret_cast<const unsigned long long*>(&c)));
    return d;
}

__device__ __forceinline__ float2 fmul2(float2 a, float2 b) {
    float2 d;
    asm("mul.rn.f32x2 %0, %1, %2;"
        : "=l"(*reinterpret_cast<unsigned long long*>(&d))
        : "l"(*reinterpret_cast<const unsigned long long*>(&a)),
          "l"(*reinterpret_cast<const unsigned long long*>(&b)));
    return d;
}

// ---------------- prep: stage A — partial column sums of C (coalesced) --------
__global__ __launch_bounds__(64)
void csum_part_kernel(const float* __restrict__ C) {
    const int d = threadIdx.x;
    const float* __restrict__ Cp = C + (size_t)blockIdx.x * 16 * DS + d;
    float s = 0.f;
    #pragma unroll
    for (int i = 0; i < 16; ++i) s += Cp[(size_t)i * DS];
    g_part[blockIdx.x * DS + d] = s;
}

// ---------------- prep: stage B + K build (f32x2 geometric chains) ------------
__global__ __launch_bounds__(64)
void kbuild_kernel(const float* __restrict__ A,
                   const float* __restrict__ Bp,
                   const float* __restrict__ log_dt) {
    __shared__ float sh_csum[DS];
    const int tid = threadIdx.x;

    {
        float s = 0.f;
        #pragma unroll 16
        for (int j = 0; j < 64; ++j) s += g_part[j * DS + tid];
        sh_csum[tid] = s;
    }
    __syncthreads();

    const int c = blockIdx.x * 64 + tid;
    const float dt = expf(log_dt[c]);

    float2 k2[LTAPS / 2];
    #pragma unroll
    for (int i = 0; i < LTAPS / 2; ++i) k2[i] = make_float2(0.f, 0.f);

    #pragma unroll 2
    for (int d = 0; d < DS; ++d) {
        const float w  = sh_csum[d] * Bp[(size_t)d * DM + c];
        const float r  = expf(A[d] * dt);
        const float r2 = r * r;
        float2 p = make_float2(w, w * r);
        const float2 rr = make_float2(r2, r2);
        #pragma unroll
        for (int i = 0; i < LTAPS / 2; ++i) {
            k2[i].x += p.x;
            k2[i].y += p.y;
            p = fmul2(p, rr);
        }
    }

    #pragma unroll
    for (int i = 0; i < LTAPS / 2; ++i) {
        g_K[(size_t)(2 * i)     * DM + c] = k2[i].x;
        g_K[(size_t)(2 * i + 1) * DM + c] = k2[i].y;
    }
}

// ---------------- conv kernel ----------------
// y[b,t,c] = D[c]*u[b,t,c] + sum_{l=0}^{63} K[l,c] * u[b, t+31-l, c]
// 512 threads. Lane map: lanes 2i,2i+1 share channel-pair p (tg differs), so
// shK[l][p] reads are 2-way same-address broadcasts WITHIN each 16-lane phase
// -> K crossbar bytes halve. u tile padded to PITCH=33 so the same-p lane
// pairs (t vs t+8) hit disjoint banks -> window reads stay full-rate.

__global__ __launch_bounds__(NTHR, 2)
void conv_kernel(const float* __restrict__ u,
                 const float* __restrict__ Dp,
                 float* __restrict__ y) {
    __shared__ float2 sh[TBLK + 64][PITCH];       // ~49.5KB u tile (padded)
    __shared__ float2 shK[LTAPS][CBLK / 2];       // 16KB K tile

    const int b  = blockIdx.z;
    const int t0 = blockIdx.x * TBLK;
    const int c0 = blockIdx.y * CBLK;
    const int tid = threadIdx.x;

    const float2* __restrict__ u2 =
        reinterpret_cast<const float2*>(u + (size_t)b * SEQ * DM + c0);

    // cooperative coalesced u-tile load; interior blocks skip predication
    if (t0 >= 32 && t0 + TBLK + 32 <= SEQ) {
        #pragma unroll
        for (int it = 0; it < (TBLK + 64) * 32 / NTHR; ++it) {
            int i  = it * NTHR + tid;
            int tt = i >> 5;
            int pp = i & 31;
            sh[tt][pp] = u2[(size_t)(t0 - 32 + tt) * (DM / 2) + pp];
        }
    } else {
        #pragma unroll
        for (int it = 0; it < (TBLK + 64) * 32 / NTHR; ++it) {
            int i  = it * NTHR + tid;
            int tt = i >> 5;
            int pp = i & 31;
            int t  = t0 - 32 + tt;
            float2 v = make_float2(0.f, 0.f);
            if (t >= 0 && t < SEQ) v = u2[(size_t)t * (DM / 2) + pp];
            sh[tt][pp] = v;
        }
    }

    // cooperative K-tile load: 64 taps x 32 pairs = 2048 float2, 4 per thread
    {
        const float2* __restrict__ gK2 =
            reinterpret_cast<const float2*>(g_K) + (c0 >> 1);
        #pragma unroll
        for (int it = 0; it < LTAPS * 32 / NTHR; ++it) {
            int i  = it * NTHR + tid;
            int l  = i >> 5;
            int pp = i & 31;
            shK[l][pp] = gK2[(size_t)l * (DM / 2) + pp];
        }
    }
    __syncthreads();

    // lane map: pairs of adjacent lanes share p; tg from lane bit 0
    const int lane = tid & 31;
    const int wrp  = tid >> 5;                                   // 0..15
    const int p    = ((wrp & 1) << 4) | ((lane & 16) >> 1) | ((lane & 15) >> 1);
    const int tg   = ((wrp >> 1) << 1) | (lane & 1);             // 0..15
    const int lt0  = 32 + tg * TT;

    const float2 d2 = reinterpret_cast<const float2*>(Dp + c0)[p];

    float2 acc[TT];
    #pragma unroll
    for (int j = 0; j < TT; ++j)
        acc[j] = fmul2(d2, sh[lt0 + j][p]);

    // register sliding window: 15 float2 covering sh[wb .. wb+14]
    float2 w[TT + G - 1];
    const int wb0 = lt0 + 32 - G;   // = lt0 + 24
    #pragma unroll
    for (int i = 0; i < TT + G - 1; ++i) w[i] = sh[wb0 + i][p];

    #pragma unroll
    for (int g = 0; g < LTAPS / G; ++g) {
        if (g > 0) {
            #pragma unroll
            for (int i = TT + G - 2; i >= G; --i) w[i] = w[i - G];
            const int wb = wb0 - g * G;
            #pragma unroll
            for (int i = 0; i < G; ++i) w[i] = sh[wb + i][p];
        }
        #pragma unroll
        for (int e = 0; e < G; ++e) {
            float2 k2 = shK[g * G + e][p];   // 2-way intra-phase broadcast
            #pragma unroll
            for (int j = 0; j < TT; ++j)
                acc[j] = ffma2(k2, w[j + (G - 1 - e)], acc[j]);
        }
    }

    float2* __restrict__ y2 =
        reinterpret_cast<float2*>(y + (size_t)b * SEQ * DM + c0);
    #pragma unroll
    for (int j = 0; j < TT; ++j) {
        int t = t0 + tg * TT + j;
        y2[(size_t)t * (DM / 2) + p] = acc[j];
    }
}

// ---------------- launch ----------------

extern "C" void kernel_launch(void* const* d_in, const int* in_sizes, int n_in,
                              void* d_out, int out_size) {
    const float* u      = (const float*)d_in[0];
    const float* A      = (const float*)d_in[1];
    const float* Bp     = (const float*)d_in[2];
    const float* C      = (const float*)d_in[3];
    const float* Dp     = (const float*)d_in[4];
    const float* log_dt = (const float*)d_in[5];
    float* y = (float*)d_out;

    csum_part_kernel<<<64, 64>>>(C);
    kbuild_kernel<<<16, 64>>>(A, Bp, log_dt);

    dim3 grid(SEQ / TBLK, DM / CBLK, B_SZ);  // (32, 16, 8)
    conv_kernel<<<grid, NTHR>>>(u, Dp, y);
}

// round 12
// speedup vs baseline: 1.1412x; 1.0418x over previous
#include <cuda_runtime.h>
#include <cstdint>

#define B_SZ 8
#define SEQ 4096
#define DM 1024
#define DS 64
#define LTAPS 64

#define TBLK 128   // time steps per block
#define CBLK 64    // channels per block (32 float2 pairs)
#define TT 8       // outputs per thread
#define NTHR 512   // conv block size
#define G 8        // tap group size

__device__ float g_part[64 * DS];   // partial C column sums
__device__ float g_K[LTAPS * DM];   // K[l][c], channel-contiguous

// ---------------- packed f32x2 ops (Blackwell FFMA2, PTX-only) ----------------

__device__ __forceinline__ float2 ffma2(float2 a, float2 b, float2 c) {
    float2 d;
    asm("fma.rn.f32x2 %0, %1, %2, %3;"
        : "=l"(*reinterpret_cast<unsigned long long*>(&d))
        : "l"(*reinterpret_cast<const unsigned long long*>(&a)),
          "l"(*reinterpret_cast<const unsigned long long*>(&b)),
          "l"(*reinterpret_cast<const unsigned long long*>(&c)));
    return d;
}

__device__ __forceinline__ float2 fmul2(float2 a, float2 b) {
    float2 d;
    asm("mul.rn.f32x2 %0, %1, %2;"
        : "=l"(*reinterpret_cast<unsigned long long*>(&d))
        : "l"(*reinterpret_cast<const unsigned long long*>(&a)),
          "l"(*reinterpret_cast<const unsigned long long*>(&b)));
    return d;
}

// ---------------- prep: stage A — partial column sums of C (coalesced) --------
__global__ __launch_bounds__(64)
void csum_part_kernel(const float* __restrict__ C) {
    const int d = threadIdx.x;
    const float* __restrict__ Cp = C + (size_t)blockIdx.x * 16 * DS + d;
    float s = 0.f;
    #pragma unroll
    for (int i = 0; i < 16; ++i) s += Cp[(size_t)i * DS];
    g_part[blockIdx.x * DS + d] = s;
}

// ---------------- prep: stage B + K build (f32x2 geometric chains) ------------
__global__ __launch_bounds__(64)
void kbuild_kernel(const float* __restrict__ A,
                   const float* __restrict__ Bp,
                   const float* __restrict__ log_dt) {
    __shared__ float sh_csum[DS];
    const int tid = threadIdx.x;

    {
        float s = 0.f;
        #pragma unroll 16
        for (int j = 0; j < 64; ++j) s += g_part[j * DS + tid];
        sh_csum[tid] = s;
    }
    __syncthreads();

    const int c = blockIdx.x * 64 + tid;
    const float dt = expf(log_dt[c]);

    float2 k2[LTAPS / 2];
    #pragma unroll
    for (int i = 0; i < LTAPS / 2; ++i) k2[i] = make_float2(0.f, 0.f);

    #pragma unroll 2
    for (int d = 0; d < DS; ++d) {
        const float w  = sh_csum[d] * Bp[(size_t)d * DM + c];
        const float r  = expf(A[d] * dt);
        const float r2 = r * r;
        float2 p = make_float2(w, w * r);
        const float2 rr = make_float2(r2, r2);
        #pragma unroll
        for (int i = 0; i < LTAPS / 2; ++i) {
            k2[i].x += p.x;
            k2[i].y += p.y;
            p = fmul2(p, rr);
        }
    }

    #pragma unroll
    for (int i = 0; i < LTAPS / 2; ++i) {
        g_K[(size_t)(2 * i)     * DM + c] = k2[i].x;
        g_K[(size_t)(2 * i + 1) * DM + c] = k2[i].y;
    }
}

// ---------------- conv kernel (R3-measured structure, verbatim: K from L2) ----
// y[b,t,c] = D[c]*u[b,t,c] + sum_{l=0}^{63} K[l,c] * u[b, t+31-l, c]
// 512 threads: 32 channel-pairs x 16 time groups x TT=8 outputs.
// u tile in shared (48KB); K read per-tap from L2 (256KB resident).

__global__ __launch_bounds__(NTHR, 2)
void conv_kernel(const float* __restrict__ u,
                 const float* __restrict__ Dp,
                 float* __restrict__ y) {
    __shared__ float2 sh[TBLK + 64][CBLK / 2];   // 48KB u tile

    const int b  = blockIdx.z;
    const int t0 = blockIdx.x * TBLK;
    const int c0 = blockIdx.y * CBLK;
    const int tid = threadIdx.x;

    const float2* __restrict__ u2 =
        reinterpret_cast<const float2*>(u + (size_t)b * SEQ * DM + c0);

    // cooperative coalesced tile load; interior blocks skip predication
    if (t0 >= 32 && t0 + TBLK + 32 <= SEQ) {
        #pragma unroll
        for (int it = 0; it < (TBLK + 64) * 32 / NTHR; ++it) {
            int i  = it * NTHR + tid;
            int tt = i >> 5;
            int p  = i & 31;
            sh[tt][p] = u2[(size_t)(t0 - 32 + tt) * (DM / 2) + p];
        }
    } else {
        #pragma unroll
        for (int it = 0; it < (TBLK + 64) * 32 / NTHR; ++it) {
            int i  = it * NTHR + tid;
            int tt = i >> 5;
            int p  = i & 31;
            int t  = t0 - 32 + tt;
            float2 v = make_float2(0.f, 0.f);
            if (t >= 0 && t < SEQ) v = u2[(size_t)t * (DM / 2) + p];
            sh[tt][p] = v;
        }
    }
    __syncthreads();

    const int p   = tid & 31;          // channel pair
    const int tg  = tid >> 5;          // time group (0..15)
    const int lt0 = 32 + tg * TT;      // shared time index of output j=0

    const float2 d2 = reinterpret_cast<const float2*>(Dp + c0)[p];

    float2 acc[TT];
    #pragma unroll
    for (int j = 0; j < TT; ++j)
        acc[j] = fmul2(d2, sh[lt0 + j][p]);

    // K pointer for this channel pair: K[l][c0+2p] as float2
    const float2* __restrict__ Kp =
        reinterpret_cast<const float2*>(g_K) + (c0 >> 1) + p;

    // register sliding window: 15 float2 covering sh[wb .. wb+14]
    float2 w[TT + G - 1];
    const int wb0 = lt0 + 32 - G;   // = lt0 + 24
    #pragma unroll
    for (int i = 0; i < TT + G - 1; ++i) w[i] = sh[wb0 + i][p];

    #pragma unroll
    for (int g = 0; g < LTAPS / G; ++g) {
        if (g > 0) {
            #pragma unroll
            for (int i = TT + G - 2; i >= G; --i) w[i] = w[i - G];
            const int wb = wb0 - g * G;
            #pragma unroll
            for (int i = 0; i < G; ++i) w[i] = sh[wb + i][p];
        }
        #pragma unroll
        for (int e = 0; e < G; ++e) {
            const int l = g * G + e;
            float2 k2 = Kp[(size_t)l * (DM / 2)];
            #pragma unroll
            for (int j = 0; j < TT; ++j)
                acc[j] = ffma2(k2, w[j + (G - 1 - e)], acc[j]);
        }
    }

    // store
    float2* __restrict__ y2 =
        reinterpret_cast<float2*>(y + (size_t)b * SEQ * DM + c0);
    #pragma unroll
    for (int j = 0; j < TT; ++j) {
        int t = t0 + tg * TT + j;
        y2[(size_t)t * (DM / 2) + p] = acc[j];
    }
}

// ---------------- launch ----------------

extern "C" void kernel_launch(void* const* d_in, const int* in_sizes, int n_in,
                              void* d_out, int out_size) {
    const float* u      = (const float*)d_in[0];
    const float* A      = (const float*)d_in[1];
    const float* Bp     = (const float*)d_in[2];
    const float* C      = (const float*)d_in[3];
    const float* Dp     = (const float*)d_in[4];
    const float* log_dt = (const float*)d_in[5];
    float* y = (float*)d_out;

    csum_part_kernel<<<64, 64>>>(C);
    kbuild_kernel<<<16, 64>>>(A, Bp, log_dt);

    dim3 grid(SEQ / TBLK, DM / CBLK, B_SZ);  // (32, 16, 8)
    conv_kernel<<<grid, NTHR>>>(u, Dp, y);
}